// round 1
// baseline (speedup 1.0000x reference)
#include <cuda_runtime.h>

#define FULL 0xffffffffu
constexpr int F = 6;
constexpr int H = 32;
constexpr int WARPS = 8;

// shared weight buffer offsets (floats)
constexpr int O_Wn = 0;       // 192
constexpr int O_bn = 192;     // 32
constexpr int O_We1 = 224;    // 2048
constexpr int O_be1 = 2272;   // 32
constexpr int O_We2 = 2304;   // 32
constexpr int O_be2 = 2336;   // 1 (pad 4)
constexpr int O_Wd1 = 2340;   // 192
constexpr int O_bd1 = 2532;   // 32
constexpr int O_Wd2 = 2564;   // 1024
constexpr int O_bd2 = 3588;   // 32
constexpr int O_Wd3 = 3620;   // 192
constexpr int O_bd3 = 3812;   // 6 (pad 8)
constexpr int O_Ws1 = 3820;   // 576
constexpr int O_bs1 = 4396;   // 32
constexpr int O_Ws2 = 4428;   // 512
constexpr int O_bs2 = 4940;   // 16
constexpr int O_Ws3 = 4956;   // 16
constexpr int O_bs3 = 4972;   // 1 (pad 4)
constexpr int W_TOT = 4976;

__device__ __forceinline__ float sigm(float x) {
    return 1.0f / (1.0f + __expf(-x));
}

__device__ __forceinline__ float wsum(float t) {
#pragma unroll
    for (int o = 16; o; o >>= 1) t += __shfl_xor_sync(FULL, t, o);
    return t;
}

// broadcast factors[idx] (idx in 0..35) from the two register slices
__device__ __forceinline__ float bselect(float fr0, float fr1, int idx) {
    // idx uniform across warp
    return __shfl_sync(FULL, (idx < 32) ? fr0 : fr1, idx & 31);
}

__global__ __launch_bounds__(WARPS * 32) void cad_kernel(
    const float* __restrict__ factors,
    const float* __restrict__ Wn,  const float* __restrict__ bn,
    const float* __restrict__ We1, const float* __restrict__ be1,
    const float* __restrict__ We2, const float* __restrict__ be2,
    const float* __restrict__ Wd1, const float* __restrict__ bd1,
    const float* __restrict__ Wd2, const float* __restrict__ bd2,
    const float* __restrict__ Wd3, const float* __restrict__ bd3,
    const float* __restrict__ Ws1, const float* __restrict__ bs1,
    const float* __restrict__ Ws2, const float* __restrict__ bs2,
    const float* __restrict__ Ws3, const float* __restrict__ bs3,
    float* __restrict__ out, int Btot)
{
    __shared__ float w[W_TOT];
    __shared__ float adj_s[WARPS][40];
    __shared__ float pred_s[WARPS][40];

    {
        const float* srcs[18] = {Wn, bn, We1, be1, We2, be2, Wd1, bd1, Wd2,
                                 bd2, Wd3, bd3, Ws1, bs1, Ws2, bs2, Ws3, bs3};
        const int offs[18] = {O_Wn, O_bn, O_We1, O_be1, O_We2, O_be2, O_Wd1,
                              O_bd1, O_Wd2, O_bd2, O_Wd3, O_bd3, O_Ws1, O_bs1,
                              O_Ws2, O_bs2, O_Ws3, O_bs3};
        const int cnts[18] = {192, 32, 2048, 32, 32, 1, 192, 32, 1024,
                              32, 192, 6, 576, 32, 512, 16, 16, 1};
        for (int a = 0; a < 18; a++)
            for (int i = threadIdx.x; i < cnts[a]; i += blockDim.x)
                w[offs[a] + i] = srcs[a][i];
    }
    __syncthreads();

    const int lane = threadIdx.x & 31;
    const int warp = threadIdx.x >> 5;
    const int b = blockIdx.x * WARPS + warp;
    if (b >= Btot) return;

    // load this sample's 36 factors into 2 register slices (coalesced)
    const float* fb = factors + (long)b * 36;
    float fr0 = fb[lane];
    float fr1 = (lane < 4) ? fb[32 + lane] : 0.0f;

    // ---- node encoder: nf[i][lane] ----
    float nf[F];
#pragma unroll
    for (int i = 0; i < F; i++) {
        float acc = w[O_bn + lane];
#pragma unroll
        for (int f = 0; f < F; f++)
            acc = fmaf(bselect(fr0, fr1, i * 6 + f), w[O_Wn + f * 32 + lane], acc);
        nf[i] = acc;
    }

    // ---- edge MLP first layer, split: u_i = nf_i @ We1[:H], v_j = nf_j @ We1[H:] ----
    float u[F], v[F];
#pragma unroll
    for (int i = 0; i < F; i++) {
        float ui = 0.0f, vi = 0.0f;
#pragma unroll
        for (int k = 0; k < H; k++) {
            float bc = __shfl_sync(FULL, nf[i], k);
            ui = fmaf(bc, w[O_We1 + k * 32 + lane], ui);
            vi = fmaf(bc, w[O_We1 + (H + k) * 32 + lane], vi);
        }
        u[i] = ui;
        v[i] = vi;
    }

    // ---- adjacency ----
    float be1l = w[O_be1 + lane];
    float we2l = w[O_We2 + lane];
    float be2v = w[O_be2];
#pragma unroll
    for (int i = 0; i < F; i++) {
#pragma unroll
        for (int j = 0; j < F; j++) {
            float a;
            if (i == j) {
                a = 0.0f;
            } else {
                float eh = fmaxf(u[i] + v[j] + be1l, 0.0f);
                a = sigm(wsum(eh * we2l) + be2v);
            }
            if (lane == 0) adj_s[warp][i * 6 + j] = a;
        }
    }
    __syncwarp();

    // coalesced adj output
    {
        float* oa = out + (long)b * 36;
        oa[lane] = adj_s[warp][lane];
        if (lane < 4) oa[32 + lane] = adj_s[warp][32 + lane];
    }

    // ---- dynamics: structured[n][i] = sum_j adj[i][j]*factors[n][j]; h1 = relu(.@Wd1+bd1) ----
    float h1[F];
#pragma unroll
    for (int n = 0; n < F; n++) {
        float acc = w[O_bd1 + lane];
#pragma unroll
        for (int i = 0; i < F; i++) {
            float s = 0.0f;
#pragma unroll
            for (int j = 0; j < F; j++)
                s = fmaf(adj_s[warp][i * 6 + j], bselect(fr0, fr1, n * 6 + j), s);
            acc = fmaf(s, w[O_Wd1 + i * 32 + lane], acc);
        }
        h1[n] = fmaxf(acc, 0.0f);
    }

    // ---- h2 = relu(h1 @ Wd2 + bd2) ----
    float h2[F];
#pragma unroll
    for (int n = 0; n < F; n++) {
        float acc = w[O_bd2 + lane];
#pragma unroll
        for (int k = 0; k < H; k++)
            acc = fmaf(__shfl_sync(FULL, h1[n], k), w[O_Wd2 + k * 32 + lane], acc);
        h2[n] = fmaxf(acc, 0.0f);
    }

    // ---- pred = h2 @ Wd3 + bd3 ----
#pragma unroll
    for (int n = 0; n < F; n++) {
#pragma unroll
        for (int f = 0; f < F; f++) {
            float t = wsum(h2[n] * w[O_Wd3 + lane * 6 + f]);
            if (lane == 0) pred_s[warp][n * 6 + f] = t + w[O_bd3 + f];
        }
    }
    __syncwarp();

    // coalesced pred output
    {
        float* op = out + (long)Btot * 36 + (long)b * 36;
        op[lane] = pred_s[warp][lane];
        if (lane < 4) op[32 + lane] = pred_s[warp][32 + lane];
    }

    // ---- anomaly scorer ----
    float ssum = 0.0f;
    float bs1l = w[O_bs1 + lane];
    float bs3v = w[O_bs3];
#pragma unroll
    for (int n = 0; n < F; n++) {
        float acc = bs1l;
#pragma unroll
        for (int k = 0; k < F; k++) {
            float fk = bselect(fr0, fr1, n * 6 + k);
            float pk = pred_s[warp][n * 6 + k];
            float dk = fabsf(fk - pk);
            acc = fmaf(fk, w[O_Ws1 + k * 32 + lane], acc);
            acc = fmaf(pk, w[O_Ws1 + (6 + k) * 32 + lane], acc);
            acc = fmaf(dk, w[O_Ws1 + (12 + k) * 32 + lane], acc);
        }
        float s1 = fmaxf(acc, 0.0f);

        float acc2 = w[O_bs2 + (lane & 15)];
#pragma unroll
        for (int k = 0; k < H; k++)
            acc2 = fmaf(__shfl_sync(FULL, s1, k), w[O_Ws2 + k * 16 + (lane & 15)], acc2);

        float t = (lane < 16) ? fmaxf(acc2, 0.0f) * w[O_Ws3 + lane] : 0.0f;
        ssum += sigm(wsum(t) + bs3v);
    }
    if (lane == 0) out[(long)Btot * 72 + b] = ssum * (1.0f / 6.0f);
}

extern "C" void kernel_launch(void* const* d_in, const int* in_sizes, int n_in,
                              void* d_out, int out_size) {
    const float* p[19];
    for (int i = 0; i < 19; i++) p[i] = (const float*)d_in[i];
    int Btot = in_sizes[0] / 36;
    int blocks = (Btot + WARPS - 1) / WARPS;
    cad_kernel<<<blocks, WARPS * 32>>>(
        p[0], p[1], p[2], p[3], p[4], p[5], p[6], p[7], p[8], p[9], p[10],
        p[11], p[12], p[13], p[14], p[15], p[16], p[17], p[18],
        (float*)d_out, Btot);
}

// round 3
// speedup vs baseline: 1.2602x; 1.2602x over previous
#include <cuda_runtime.h>

#define FULL 0xffffffffu
constexpr int NW = 8;  // warps per block

__device__ __forceinline__ float sigm(float x) { return 1.0f / (1.0f + __expf(-x)); }

__device__ __forceinline__ float wsum(float t) {
#pragma unroll
    for (int o = 16; o; o >>= 1) t += __shfl_xor_sync(FULL, t, o);
    return t;
}

#define FMA4(acc, vec, arr, base)                  \
    acc = fmaf((vec).x, (arr)[(base) + 0], acc);   \
    acc = fmaf((vec).y, (arr)[(base) + 1], acc);   \
    acc = fmaf((vec).z, (arr)[(base) + 2], acc);   \
    acc = fmaf((vec).w, (arr)[(base) + 3], acc);

__global__ __launch_bounds__(NW * 32) void cad_kernel(
    const float* __restrict__ factors,
    const float* __restrict__ Wn,  const float* __restrict__ bn,
    const float* __restrict__ We1, const float* __restrict__ be1,
    const float* __restrict__ We2, const float* __restrict__ be2,
    const float* __restrict__ Wd1, const float* __restrict__ bd1,
    const float* __restrict__ Wd2, const float* __restrict__ bd2,
    const float* __restrict__ Wd3, const float* __restrict__ bd3,
    const float* __restrict__ Ws1, const float* __restrict__ bs1,
    const float* __restrict__ Ws2, const float* __restrict__ bs2,
    const float* __restrict__ Ws3, const float* __restrict__ bs3,
    float* __restrict__ out, int Btot)
{
    // transposed, pad-aligned weight copies. __align__(16) is load-bearing:
    // float4 reinterpret-casts require 16B-aligned bases (R2 failed without it).
    __shared__ __align__(16) float wnT[32 * 12];    // Wn^T   [lane][f]  stride 12
    __shared__ __align__(16) float we1T[32 * 68];   // We1^T  [lane][k]  stride 68
    __shared__ __align__(16) float wd1T[32 * 12];   // Wd1^T  [lane][i]
    __shared__ __align__(16) float wd2T[32 * 36];   // Wd2^T  [lane][k]  stride 36
    __shared__ __align__(16) float wd3P[32 * 12];   // Wd3    [lane][f]
    __shared__ __align__(16) float ws1T[32 * 20];   // Ws1^T  [lane][k]  stride 20
    __shared__ __align__(16) float ws2T[16 * 36];   // Ws2^T  [m][k]     stride 36
    __shared__ float bnS[32], be1S[32], we2S[32], bd1S[32], bd2S[32], bs1S[32];
    __shared__ float bs2S[16], ws3S[16], bd3S[8], scal[2];
    __shared__ __align__(16) float fs[NW][40];     // per-warp factors
    __shared__ __align__(16) float buf[NW][192];   // per-warp nf / h1 / s1 staging
    __shared__ __align__(16) float adjS[NW][40];   // per-warp adj staging
    __shared__ __align__(16) float spS[NW][40];    // per-warp structured staging

    const int tid = threadIdx.x;

    // ---- cooperative weight staging / transpose ----
    for (int idx = tid; idx < 2048; idx += NW * 32) {  // We1 (64,32)
        int k = idx >> 5, l = idx & 31;
        we1T[l * 68 + k] = We1[idx];
    }
    for (int idx = tid; idx < 1024; idx += NW * 32) {  // Wd2 (32,32)
        int k = idx >> 5, l = idx & 31;
        wd2T[l * 36 + k] = Wd2[idx];
    }
    for (int idx = tid; idx < 576; idx += NW * 32) {   // Ws1 (18,32)
        int k = idx >> 5, l = idx & 31;
        ws1T[l * 20 + k] = Ws1[idx];
    }
    for (int idx = tid; idx < 512; idx += NW * 32) {   // Ws2 (32,16)
        int k = idx >> 4, m = idx & 15;
        ws2T[m * 36 + k] = Ws2[idx];
    }
    for (int idx = tid; idx < 192; idx += NW * 32) {   // Wn, Wd1 (6,32); Wd3 (32,6)
        int f = idx >> 5, l = idx & 31;
        wnT[l * 12 + f]  = Wn[idx];
        wd1T[l * 12 + f] = Wd1[idx];
        int k3 = idx / 6, f3 = idx - k3 * 6;
        wd3P[k3 * 12 + f3] = Wd3[idx];
    }
    if (tid < 32) {
        bnS[tid] = bn[tid];  be1S[tid] = be1[tid]; we2S[tid] = We2[tid];
        bd1S[tid] = bd1[tid]; bd2S[tid] = bd2[tid]; bs1S[tid] = bs1[tid];
    }
    if (tid < 16) { bs2S[tid] = bs2[tid]; ws3S[tid] = Ws3[tid]; }
    if (tid < 6)  { bd3S[tid] = bd3[tid]; }
    if (tid == 0) { scal[0] = be2[0]; scal[1] = bs3[0]; }
    __syncthreads();

    const int lane = tid & 31;
    const int w = tid >> 5;
    const int b = blockIdx.x * NW + w;
    if (b >= Btot) return;

    // ---- load + stage factors ----
    const float* fb = factors + (size_t)b * 36;
    fs[w][lane] = fb[lane];
    if (lane < 4) fs[w][32 + lane] = fb[32 + lane];
    __syncwarp();

    const float bnl = bnS[lane], be1l = be1S[lane], we2l = we2S[lane];
    const float bd1l = bd1S[lane], bd2l = bd2S[lane], bs1l = bs1S[lane];
    const float be2v = scal[0], bs3v = scal[1];

    // ---- node encoder -> buf = nf[i][lane] ----
    {
        float4 t0 = *(const float4*)&wnT[lane * 12];
        float2 t1 = *(const float2*)&wnT[lane * 12 + 4];
        float wnc[6] = {t0.x, t0.y, t0.z, t0.w, t1.x, t1.y};
#pragma unroll
        for (int i = 0; i < 6; i++) {
            float acc = bnl;
#pragma unroll
            for (int f = 0; f < 6; f++)
                acc = fmaf(fs[w][i * 6 + f], wnc[f], acc);
            buf[w][i * 32 + lane] = acc;
        }
    }
    __syncwarp();

    // ---- edge layer: u_i, v_i (split of concat @ We1) ----
    float u[6], v[6];
    {
        float wu[32], wv[32];
#pragma unroll
        for (int t = 0; t < 8; t++) {
            float4 a = *(const float4*)&we1T[lane * 68 + 4 * t];
            float4 c = *(const float4*)&we1T[lane * 68 + 32 + 4 * t];
            wu[4 * t] = a.x; wu[4 * t + 1] = a.y; wu[4 * t + 2] = a.z; wu[4 * t + 3] = a.w;
            wv[4 * t] = c.x; wv[4 * t + 1] = c.y; wv[4 * t + 2] = c.z; wv[4 * t + 3] = c.w;
        }
#pragma unroll
        for (int i = 0; i < 6; i++) {
            float ui = 0.0f, vi = 0.0f;
#pragma unroll
            for (int t = 0; t < 8; t++) {
                float4 nv = *(const float4*)&buf[w][i * 32 + 4 * t];
                FMA4(ui, nv, wu, 4 * t);
                FMA4(vi, nv, wv, 4 * t);
            }
            u[i] = ui; v[i] = vi;
        }
    }

    // ---- adjacency: 30 edge reductions; extract per-lane value via SEL ----
    float aout = 0.0f, aout2 = 0.0f;
#pragma unroll
    for (int i = 0; i < 6; i++) {
#pragma unroll
        for (int j = 0; j < 6; j++) {
            if (i == j) continue;
            float eh = fmaxf(u[i] + v[j] + be1l, 0.0f);
            float a = sigm(wsum(eh * we2l) + be2v);
            const int e = i * 6 + j;
            if (e < 32) aout = (lane == e) ? a : aout;
            else        aout2 = (lane == e - 32) ? a : aout2;
        }
    }
    out[(size_t)b * 36 + lane] = aout;
    adjS[w][lane] = aout;
    if (lane < 4) {
        out[(size_t)b * 36 + 32 + lane] = aout2;
        adjS[w][32 + lane] = aout2;
    }
    __syncwarp();

    // ---- structured (transposed: lane = (n,i) pair) ----
    {
        int n1 = lane / 6, i1 = lane - n1 * 6;
        float s = 0.0f;
#pragma unroll
        for (int j = 0; j < 6; j++)
            s = fmaf(adjS[w][i1 * 6 + j], fs[w][n1 * 6 + j], s);
        spS[w][lane] = s;
        if (lane < 4) {
            int e2 = 32 + lane, n2 = e2 / 6, i2 = e2 - n2 * 6;
            float s2 = 0.0f;
#pragma unroll
            for (int j = 0; j < 6; j++)
                s2 = fmaf(adjS[w][i2 * 6 + j], fs[w][n2 * 6 + j], s2);
            spS[w][e2] = s2;
        }
    }
    __syncwarp();

    // ---- h1 = relu(structured @ Wd1 + bd1) -> buf ----
    {
        float4 t0 = *(const float4*)&wd1T[lane * 12];
        float2 t1 = *(const float2*)&wd1T[lane * 12 + 4];
        float wd1c[6] = {t0.x, t0.y, t0.z, t0.w, t1.x, t1.y};
#pragma unroll
        for (int n = 0; n < 6; n++) {
            float acc = bd1l;
#pragma unroll
            for (int i = 0; i < 6; i++)
                acc = fmaf(spS[w][n * 6 + i], wd1c[i], acc);
            buf[w][n * 32 + lane] = fmaxf(acc, 0.0f);
        }
    }
    __syncwarp();

    // ---- h2 = relu(h1 @ Wd2 + bd2) ----
    float h2r[6];
    {
        float wd2c[32];
#pragma unroll
        for (int t = 0; t < 8; t++) {
            float4 a = *(const float4*)&wd2T[lane * 36 + 4 * t];
            wd2c[4 * t] = a.x; wd2c[4 * t + 1] = a.y;
            wd2c[4 * t + 2] = a.z; wd2c[4 * t + 3] = a.w;
        }
#pragma unroll
        for (int n = 0; n < 6; n++) {
            float acc = bd2l;
#pragma unroll
            for (int t = 0; t < 8; t++) {
                float4 hv = *(const float4*)&buf[w][n * 32 + 4 * t];
                FMA4(acc, hv, wd2c, 4 * t);
            }
            h2r[n] = fmaxf(acc, 0.0f);
        }
    }

    // ---- pred = h2 @ Wd3 + bd3 (wsum; value lands in all lanes) ----
    float pred[36];
    float pout = 0.0f, pout2 = 0.0f;
    {
        float4 t0 = *(const float4*)&wd3P[lane * 12];
        float2 t1 = *(const float2*)&wd3P[lane * 12 + 4];
        float wd3p[6] = {t0.x, t0.y, t0.z, t0.w, t1.x, t1.y};
        float bd3r[6];
#pragma unroll
        for (int f = 0; f < 6; f++) bd3r[f] = bd3S[f];
#pragma unroll
        for (int n = 0; n < 6; n++) {
#pragma unroll
            for (int f = 0; f < 6; f++) {
                float t = wsum(h2r[n] * wd3p[f]) + bd3r[f];
                pred[n * 6 + f] = t;
                const int e = n * 6 + f;
                if (e < 32) pout = (lane == e) ? t : pout;
                else        pout2 = (lane == e - 32) ? t : pout2;
            }
        }
    }
    {
        float* op = out + (size_t)Btot * 36 + (size_t)b * 36;
        op[lane] = pout;
        if (lane < 4) op[32 + lane] = pout2;
    }

    // ---- anomaly scorer ----
    float ssum = 0.0f;
    {
        float ws1c[18];
#pragma unroll
        for (int t = 0; t < 4; t++) {
            float4 a = *(const float4*)&ws1T[lane * 20 + 4 * t];
            ws1c[4 * t] = a.x; ws1c[4 * t + 1] = a.y;
            ws1c[4 * t + 2] = a.z; ws1c[4 * t + 3] = a.w;
        }
        {
            float2 a = *(const float2*)&ws1T[lane * 20 + 16];
            ws1c[16] = a.x; ws1c[17] = a.y;
        }
        float s1r[6];
#pragma unroll
        for (int n = 0; n < 6; n++) {
            float acc = bs1l;
#pragma unroll
            for (int k = 0; k < 6; k++) {
                float fk = fs[w][n * 6 + k];
                float pk = pred[n * 6 + k];
                float dk = fabsf(fk - pk);
                acc = fmaf(fk, ws1c[k], acc);
                acc = fmaf(pk, ws1c[6 + k], acc);
                acc = fmaf(dk, ws1c[12 + k], acc);
            }
            s1r[n] = fmaxf(acc, 0.0f);
        }
        __syncwarp();  // h2 reads of buf are done; safe to overwrite
#pragma unroll
        for (int n = 0; n < 6; n++) buf[w][n * 32 + lane] = s1r[n];
        __syncwarp();

        float ws2c[32];
#pragma unroll
        for (int t = 0; t < 8; t++) {
            float4 a = *(const float4*)&ws2T[(lane & 15) * 36 + 4 * t];
            ws2c[4 * t] = a.x; ws2c[4 * t + 1] = a.y;
            ws2c[4 * t + 2] = a.z; ws2c[4 * t + 3] = a.w;
        }
        float bs2l = bs2S[lane & 15];
        float ws3l = (lane < 16) ? ws3S[lane] : 0.0f;
#pragma unroll
        for (int n = 0; n < 6; n++) {
            float acc = bs2l;
#pragma unroll
            for (int t = 0; t < 8; t++) {
                float4 sv = *(const float4*)&buf[w][n * 32 + 4 * t];
                FMA4(acc, sv, ws2c, 4 * t);
            }
            float tt = fmaxf(acc, 0.0f) * ws3l;  // lanes >= 16 contribute 0
            ssum += sigm(wsum(tt) + bs3v);
        }
    }
    if (lane == 0) out[(size_t)Btot * 72 + b] = ssum * (1.0f / 6.0f);
}

extern "C" void kernel_launch(void* const* d_in, const int* in_sizes, int n_in,
                              void* d_out, int out_size) {
    const float* p[19];
    for (int i = 0; i < 19; i++) p[i] = (const float*)d_in[i];
    int Btot = in_sizes[0] / 36;
    int blocks = (Btot + NW - 1) / NW;
    cad_kernel<<<blocks, NW * 32>>>(
        p[0], p[1], p[2], p[3], p[4], p[5], p[6], p[7], p[8], p[9], p[10],
        p[11], p[12], p[13], p[14], p[15], p[16], p[17], p[18],
        (float*)d_out, Btot);
}

// round 4
// speedup vs baseline: 1.3618x; 1.0807x over previous
#include <cuda_runtime.h>

#define FULL 0xffffffffu
constexpr int NW = 8;    // warps per block
constexpr int SPW = 8;   // samples per warp

// per-warp activation region offsets (floats); total 768
constexpr int AFS  = 0;    // 40  factors
constexpr int ANF  = 40;   // 192 nf / h1 / s1 (i*32+k, float4-broadcast reads)
constexpr int AUV  = 232;  // u at +0 (stride 36), v at +224 (stride 36); h2S overlays u
constexpr int AADJ = 672;  // 40 adjacency
constexpr int ASP  = 712;  // 40 structured; predS overlays
constexpr int ACT  = 768;

__device__ __forceinline__ float sigm(float x) { return 1.0f / (1.0f + __expf(-x)); }

__device__ __forceinline__ float wsum(float t) {
#pragma unroll
    for (int o = 16; o; o >>= 1) t += __shfl_xor_sync(FULL, t, o);
    return t;
}

#define FMA4(acc, vec, arr, base)                  \
    acc = fmaf((vec).x, (arr)[(base) + 0], acc);   \
    acc = fmaf((vec).y, (arr)[(base) + 1], acc);   \
    acc = fmaf((vec).z, (arr)[(base) + 2], acc);   \
    acc = fmaf((vec).w, (arr)[(base) + 3], acc);

#define LD4(arr, dst, off)                                        \
    { float4 _a = *(const float4*)&(arr)[off];                    \
      (dst)[0] = _a.x; (dst)[1] = _a.y; (dst)[2] = _a.z; (dst)[3] = _a.w; }

__global__ __launch_bounds__(NW * 32) void cad_kernel(
    const float* __restrict__ factors,
    const float* __restrict__ Wn,  const float* __restrict__ bn,
    const float* __restrict__ We1, const float* __restrict__ be1,
    const float* __restrict__ We2, const float* __restrict__ be2,
    const float* __restrict__ Wd1, const float* __restrict__ bd1,
    const float* __restrict__ Wd2, const float* __restrict__ bd2,
    const float* __restrict__ Wd3, const float* __restrict__ bd3,
    const float* __restrict__ Ws1, const float* __restrict__ bs1,
    const float* __restrict__ Ws2, const float* __restrict__ bs2,
    const float* __restrict__ Ws3, const float* __restrict__ bs3,
    float* __restrict__ out, int Btot)
{
    __shared__ __align__(16) float wnT[32 * 12];     // Wn^T  [lane][f]
    __shared__ __align__(16) float we1T[32 * 68];    // We1^T [lane][k] (k<64)
    __shared__ __align__(16) float wd1T[32 * 12];    // Wd1^T [lane][i]
    __shared__ __align__(16) float wd2T[32 * 36];    // Wd2^T [lane][k]
    __shared__ __align__(16) float wd3F[6 * 36];     // Wd3^T [f][k] stride 36
    __shared__ __align__(16) float ws1T[32 * 20];    // Ws1^T [lane][k] (k<18)
    __shared__ __align__(16) float ws2T[16 * 36];    // Ws2^T [m][k]
    __shared__ __align__(16) float we2S[32];
    __shared__ float bnS[32], be1S[32], bd1S[32], bd2S[32], bs1S[32];
    __shared__ float bs2S[16], ws3S[16], bd3S[8], scal[2];
    __shared__ __align__(16) float act[NW][ACT];

    const int tid = threadIdx.x;

    // ---- weight staging / transposes ----
    for (int idx = tid; idx < 2048; idx += NW * 32) {  // We1 (64,32)
        int k = idx >> 5, l = idx & 31;
        we1T[l * 68 + k] = We1[idx];
    }
    for (int idx = tid; idx < 1024; idx += NW * 32) {  // Wd2 (32,32)
        int k = idx >> 5, l = idx & 31;
        wd2T[l * 36 + k] = Wd2[idx];
    }
    for (int idx = tid; idx < 576; idx += NW * 32) {   // Ws1 (18,32)
        int k = idx >> 5, l = idx & 31;
        ws1T[l * 20 + k] = Ws1[idx];
    }
    for (int idx = tid; idx < 512; idx += NW * 32) {   // Ws2 (32,16)
        int k = idx >> 4, m = idx & 15;
        ws2T[m * 36 + k] = Ws2[idx];
    }
    for (int idx = tid; idx < 192; idx += NW * 32) {   // Wn, Wd1 (6,32); Wd3 (32,6)
        int f = idx >> 5, l = idx & 31;
        wnT[l * 12 + f]  = Wn[idx];
        wd1T[l * 12 + f] = Wd1[idx];
        int k3 = idx / 6, f3 = idx - k3 * 6;
        wd3F[f3 * 36 + k3] = Wd3[idx];
    }
    if (tid < 32) {
        bnS[tid] = bn[tid];  be1S[tid] = be1[tid]; we2S[tid] = We2[tid];
        bd1S[tid] = bd1[tid]; bd2S[tid] = bd2[tid]; bs1S[tid] = bs1[tid];
    }
    if (tid < 16) { bs2S[tid] = bs2[tid]; ws3S[tid] = Ws3[tid]; }
    if (tid < 6)  { bd3S[tid] = bd3[tid]; }
    if (tid == 0) { scal[0] = be2[0]; scal[1] = bs3[0]; }
    __syncthreads();

    const int lane = tid & 31;
    const int w = tid >> 5;
    float* A = act[w];

    // lane -> element maps (e = lane for e<32; lanes 0..3 also do e = 32+lane)
    const int i1 = lane / 6, j1 = lane - i1 * 6;      // (row, col) for e = lane
    const int j2 = (lane < 4) ? lane + 2 : 2;         // e2 = 32+lane -> (5, lane+2)

    // ---- hoist per-lane weight columns into registers (once per kernel) ----
    float wnc[6], wd1c[6];
    {
        float4 t0 = *(const float4*)&wnT[lane * 12];
        float2 t1 = *(const float2*)&wnT[lane * 12 + 4];
        wnc[0]=t0.x; wnc[1]=t0.y; wnc[2]=t0.z; wnc[3]=t0.w; wnc[4]=t1.x; wnc[5]=t1.y;
        float4 s0 = *(const float4*)&wd1T[lane * 12];
        float2 s1 = *(const float2*)&wd1T[lane * 12 + 4];
        wd1c[0]=s0.x; wd1c[1]=s0.y; wd1c[2]=s0.z; wd1c[3]=s0.w; wd1c[4]=s1.x; wd1c[5]=s1.y;
    }
    float wu[32], wv[32], wd2c[32], ws2c[32], wd3c[32];
#pragma unroll
    for (int t = 0; t < 8; t++) {
        LD4(we1T, wu + 4 * t, lane * 68 + 4 * t);
        LD4(we1T, wv + 4 * t, lane * 68 + 32 + 4 * t);
        LD4(wd2T, wd2c + 4 * t, lane * 36 + 4 * t);
        LD4(ws2T, ws2c + 4 * t, (lane & 15) * 36 + 4 * t);
        LD4(wd3F, wd3c + 4 * t, j1 * 36 + 4 * t);
    }
    float ws1c[18];
#pragma unroll
    for (int t = 0; t < 4; t++) LD4(ws1T, ws1c + 4 * t, lane * 20 + 4 * t);
    {
        float2 a = *(const float2*)&ws1T[lane * 20 + 16];
        ws1c[16] = a.x; ws1c[17] = a.y;
    }
    const float bnl = bnS[lane], be1l = be1S[lane];
    const float bd1l = bd1S[lane], bd2l = bd2S[lane], bs1l = bs1S[lane];
    const float bs2l = bs2S[lane & 15];
    const float ws3l = (lane < 16) ? ws3S[lane] : 0.0f;
    const float bd3l = bd3S[j1], bd3l2 = bd3S[j2];
    const float be2v = scal[0], bs3v = scal[1];

    const size_t predBase = (size_t)Btot * 36;
    const size_t scoreBase = (size_t)Btot * 72;

    for (int s = 0; s < SPW; s++) {
        const int b = (blockIdx.x * NW + w) * SPW + s;
        if (b >= Btot) break;

        // ---- stage factors ----
        const float* fb = factors + (size_t)b * 36;
        A[AFS + lane] = fb[lane];
        if (lane < 4) A[AFS + 32 + lane] = fb[32 + lane];
        __syncwarp();

        // ---- node encoder: nf[i][lane] ----
#pragma unroll
        for (int i = 0; i < 6; i++) {
            float acc = bnl;
#pragma unroll
            for (int f = 0; f < 6; f++)
                acc = fmaf(A[AFS + i * 6 + f], wnc[f], acc);
            A[ANF + i * 32 + lane] = acc;
        }
        __syncwarp();

        // ---- u,v (lane = hidden); fold be1 into u ----
#pragma unroll
        for (int i = 0; i < 6; i++) {
            float ui = be1l, vi = 0.0f;
#pragma unroll
            for (int t = 0; t < 8; t++) {
                float4 nv = *(const float4*)&A[ANF + i * 32 + 4 * t];
                FMA4(ui, nv, wu, 4 * t);
                FMA4(vi, nv, wv, 4 * t);
            }
            A[AUV + i * 36 + lane] = ui;
            A[AUV + 224 + i * 36 + lane] = vi;
        }
        __syncwarp();

        // ---- adjacency (lane = edge): k-loop over hidden ----
        {
            float acc1 = 0.0f, acc2 = 0.0f;
#pragma unroll
            for (int t = 0; t < 8; t++) {
                float4 w2 = *(const float4*)&we2S[4 * t];
                float4 a1 = *(const float4*)&A[AUV + i1 * 36 + 4 * t];
                float4 b1 = *(const float4*)&A[AUV + 224 + j1 * 36 + 4 * t];
                acc1 = fmaf(fmaxf(a1.x + b1.x, 0.0f), w2.x, acc1);
                acc1 = fmaf(fmaxf(a1.y + b1.y, 0.0f), w2.y, acc1);
                acc1 = fmaf(fmaxf(a1.z + b1.z, 0.0f), w2.z, acc1);
                acc1 = fmaf(fmaxf(a1.w + b1.w, 0.0f), w2.w, acc1);
                float4 a2 = *(const float4*)&A[AUV + 5 * 36 + 4 * t];
                float4 b2 = *(const float4*)&A[AUV + 224 + j2 * 36 + 4 * t];
                acc2 = fmaf(fmaxf(a2.x + b2.x, 0.0f), w2.x, acc2);
                acc2 = fmaf(fmaxf(a2.y + b2.y, 0.0f), w2.y, acc2);
                acc2 = fmaf(fmaxf(a2.z + b2.z, 0.0f), w2.z, acc2);
                acc2 = fmaf(fmaxf(a2.w + b2.w, 0.0f), w2.w, acc2);
            }
            float a1v = (i1 == j1) ? 0.0f : sigm(acc1 + be2v);
            float a2v = (lane == 3) ? 0.0f : sigm(acc2 + be2v);  // e=35 is diagonal
            A[AADJ + lane] = a1v;
            out[(size_t)b * 36 + lane] = a1v;
            if (lane < 4) {
                A[AADJ + 32 + lane] = a2v;
                out[(size_t)b * 36 + 32 + lane] = a2v;
            }
        }
        __syncwarp();

        // ---- structured (lane = (n,i) = (i1,j1)) ----
        {
            float sv = 0.0f, sv2 = 0.0f;
#pragma unroll
            for (int j = 0; j < 6; j++) {
                sv  = fmaf(A[AADJ + j1 * 6 + j], A[AFS + i1 * 6 + j], sv);
                sv2 = fmaf(A[AADJ + j2 * 6 + j], A[AFS + 5 * 6 + j], sv2);
            }
            A[ASP + lane] = sv;
            if (lane < 4) A[ASP + 32 + lane] = sv2;
        }
        __syncwarp();

        // ---- h1 = relu(structured @ Wd1 + bd1) (lane = hidden) ----
#pragma unroll
        for (int n = 0; n < 6; n++) {
            float acc = bd1l;
#pragma unroll
            for (int i = 0; i < 6; i++)
                acc = fmaf(A[ASP + n * 6 + i], wd1c[i], acc);
            A[ANF + n * 32 + lane] = fmaxf(acc, 0.0f);
        }
        __syncwarp();

        // ---- h2 = relu(h1 @ Wd2 + bd2) -> h2S (stride 36, overlays u/v) ----
#pragma unroll
        for (int n = 0; n < 6; n++) {
            float acc = bd2l;
#pragma unroll
            for (int t = 0; t < 8; t++) {
                float4 hv = *(const float4*)&A[ANF + n * 32 + 4 * t];
                FMA4(acc, hv, wd2c, 4 * t);
            }
            A[AUV + n * 36 + lane] = fmaxf(acc, 0.0f);
        }
        __syncwarp();

        // ---- pred (lane = (n,f) = (i1,j1)): k-loop over hidden ----
        {
            float acc1 = 0.0f, acc2 = 0.0f;
#pragma unroll
            for (int t = 0; t < 8; t++) {
                float4 hv = *(const float4*)&A[AUV + i1 * 36 + 4 * t];
                FMA4(acc1, hv, wd3c, 4 * t);
                float4 h5 = *(const float4*)&A[AUV + 5 * 36 + 4 * t];
                float4 w3 = *(const float4*)&wd3F[j2 * 36 + 4 * t];
                acc2 = fmaf(h5.x, w3.x, acc2);
                acc2 = fmaf(h5.y, w3.y, acc2);
                acc2 = fmaf(h5.z, w3.z, acc2);
                acc2 = fmaf(h5.w, w3.w, acc2);
            }
            float p1 = acc1 + bd3l;
            float p2 = acc2 + bd3l2;
            A[ASP + lane] = p1;   // predS overlays structured (dead)
            float* op = out + predBase + (size_t)b * 36;
            op[lane] = p1;
            if (lane < 4) {
                A[ASP + 32 + lane] = p2;
                op[32 + lane] = p2;
            }
        }
        __syncwarp();

        // ---- scorer layer 1 (lane = hidden) -> s1 in ANF ----
#pragma unroll
        for (int n = 0; n < 6; n++) {
            float acc = bs1l;
#pragma unroll
            for (int k = 0; k < 6; k++) {
                float fk = A[AFS + n * 6 + k];
                float pk = A[ASP + n * 6 + k];
                float dk = fabsf(fk - pk);
                acc = fmaf(fk, ws1c[k], acc);
                acc = fmaf(pk, ws1c[6 + k], acc);
                acc = fmaf(dk, ws1c[12 + k], acc);
            }
            A[ANF + n * 32 + lane] = fmaxf(acc, 0.0f);
        }
        __syncwarp();

        // ---- scorer layers 2+3 ----
        float ssum = 0.0f;
#pragma unroll
        for (int n = 0; n < 6; n++) {
            float acc = bs2l;
#pragma unroll
            for (int t = 0; t < 8; t++) {
                float4 sv = *(const float4*)&A[ANF + n * 32 + 4 * t];
                FMA4(acc, sv, ws2c, 4 * t);
            }
            float tt = fmaxf(acc, 0.0f) * ws3l;  // lanes >= 16 contribute 0
            ssum += sigm(wsum(tt) + bs3v);
        }
        if (lane == 0) out[scoreBase + b] = ssum * (1.0f / 6.0f);
        __syncwarp();
    }
}

extern "C" void kernel_launch(void* const* d_in, const int* in_sizes, int n_in,
                              void* d_out, int out_size) {
    const float* p[19];
    for (int i = 0; i < 19; i++) p[i] = (const float*)d_in[i];
    int Btot = in_sizes[0] / 36;
    int per_block = NW * SPW;
    int blocks = (Btot + per_block - 1) / per_block;
    cad_kernel<<<blocks, NW * 32>>>(
        p[0], p[1], p[2], p[3], p[4], p[5], p[6], p[7], p[8], p[9], p[10],
        p[11], p[12], p[13], p[14], p[15], p[16], p[17], p[18],
        (float*)d_out, Btot);
}

// round 5
// speedup vs baseline: 1.5044x; 1.1047x over previous
#include <cuda_runtime.h>

#define FULL 0xffffffffu
constexpr int NW = 8;    // warps per block
constexpr int SPW = 8;   // samples per warp

// per-warp activation region offsets (floats); all 16B-aligned
constexpr int FSP = 0;    // factors, 6 rows stride 8 (48)
constexpr int ANF = 48;   // nf / h1 / s1, i*32+lane (192)
constexpr int AU  = 240;  // u / h2, 6 rows stride 36 (up to 451)
constexpr int AV  = 464;  // v, 6 rows stride 36 (up to 675)
constexpr int ADJ = 680;  // adjacency, rows stride 8 (48)
constexpr int ASP = 728;  // structured / pred, rows stride 8 (48)
constexpr int ACT = 784;

__device__ __forceinline__ float sigm(float x) { return 1.0f / (1.0f + __expf(-x)); }

__device__ __forceinline__ float wsum(float t) {
#pragma unroll
    for (int o = 16; o; o >>= 1) t += __shfl_xor_sync(FULL, t, o);
    return t;
}

#define FMA4(acc, vec, arr, base)                  \
    acc = fmaf((vec).x, (arr)[(base) + 0], acc);   \
    acc = fmaf((vec).y, (arr)[(base) + 1], acc);   \
    acc = fmaf((vec).z, (arr)[(base) + 2], acc);   \
    acc = fmaf((vec).w, (arr)[(base) + 3], acc);

#define FMA4V(acc, vec, wv)                        \
    acc = fmaf((vec).x, (wv).x, acc);              \
    acc = fmaf((vec).y, (wv).y, acc);              \
    acc = fmaf((vec).z, (wv).z, acc);              \
    acc = fmaf((vec).w, (wv).w, acc);

#define LD4(arr, dst, off)                                        \
    { float4 _a = *(const float4*)&(arr)[off];                    \
      (dst)[0] = _a.x; (dst)[1] = _a.y; (dst)[2] = _a.z; (dst)[3] = _a.w; }

// dot6 of two (float4,float2) row reads
#define DOT6(acc, r4, r2, q4, q2)                  \
    acc = fmaf((r4).x, (q4).x, acc);               \
    acc = fmaf((r4).y, (q4).y, acc);               \
    acc = fmaf((r4).z, (q4).z, acc);               \
    acc = fmaf((r4).w, (q4).w, acc);               \
    acc = fmaf((r2).x, (q2).x, acc);               \
    acc = fmaf((r2).y, (q2).y, acc);

__global__ __launch_bounds__(NW * 32, 2) void cad_kernel(
    const float* __restrict__ factors,
    const float* __restrict__ Wn,  const float* __restrict__ bn,
    const float* __restrict__ We1, const float* __restrict__ be1,
    const float* __restrict__ We2, const float* __restrict__ be2,
    const float* __restrict__ Wd1, const float* __restrict__ bd1,
    const float* __restrict__ Wd2, const float* __restrict__ bd2,
    const float* __restrict__ Wd3, const float* __restrict__ bd3,
    const float* __restrict__ Ws1, const float* __restrict__ bs1,
    const float* __restrict__ Ws2, const float* __restrict__ bs2,
    const float* __restrict__ Ws3, const float* __restrict__ bs3,
    float* __restrict__ out, int Btot)
{
    __shared__ __align__(16) float wnT[32 * 12];     // Wn^T  [lane][f]
    __shared__ __align__(16) float we1T[32 * 68];    // We1^T [lane][k]
    __shared__ __align__(16) float wd1T[32 * 12];    // Wd1^T [lane][i]
    __shared__ __align__(16) float wd2T[32 * 36];    // Wd2^T [lane][k]
    __shared__ __align__(16) float wd3F[6 * 36];     // Wd3^T [f][k]
    __shared__ __align__(16) float ws1T[32 * 20];    // Ws1^T [lane][k]
    __shared__ __align__(16) float ws2T[16 * 36];    // Ws2^T [m][k]
    __shared__ __align__(16) float we2S[32];
    __shared__ float bnS[32], be1S[32], bd1S[32], bd2S[32], bs1S[32];
    __shared__ float bs2S[16], ws3S[16], bd3S[8], scal[2];
    __shared__ __align__(16) float act[NW][ACT];

    const int tid = threadIdx.x;

    // ---- weight staging / transposes ----
    for (int idx = tid; idx < 2048; idx += NW * 32) {
        int k = idx >> 5, l = idx & 31;
        we1T[l * 68 + k] = We1[idx];
    }
    for (int idx = tid; idx < 1024; idx += NW * 32) {
        int k = idx >> 5, l = idx & 31;
        wd2T[l * 36 + k] = Wd2[idx];
    }
    for (int idx = tid; idx < 576; idx += NW * 32) {
        int k = idx >> 5, l = idx & 31;
        ws1T[l * 20 + k] = Ws1[idx];
    }
    for (int idx = tid; idx < 512; idx += NW * 32) {
        int k = idx >> 4, m = idx & 15;
        ws2T[m * 36 + k] = Ws2[idx];
    }
    for (int idx = tid; idx < 192; idx += NW * 32) {
        int f = idx >> 5, l = idx & 31;
        wnT[l * 12 + f]  = Wn[idx];
        wd1T[l * 12 + f] = Wd1[idx];
        int k3 = idx / 6, f3 = idx - k3 * 6;
        wd3F[f3 * 36 + k3] = Wd3[idx];
    }
    if (tid < 32) {
        bnS[tid] = bn[tid];  be1S[tid] = be1[tid]; we2S[tid] = We2[tid];
        bd1S[tid] = bd1[tid]; bd2S[tid] = bd2[tid]; bs1S[tid] = bs1[tid];
    }
    if (tid < 16) { bs2S[tid] = bs2[tid]; ws3S[tid] = Ws3[tid]; }
    if (tid < 6)  { bd3S[tid] = bd3[tid]; }
    if (tid == 0) { scal[0] = be2[0]; scal[1] = bs3[0]; }
    __syncthreads();

    const int lane = tid & 31;
    const int w = tid >> 5;
    float* A = act[w];

    const int i1 = lane / 6, j1 = lane - i1 * 6;   // element e = lane
    const int j2 = (lane < 4) ? lane + 2 : 2;      // element 32+lane -> (5, j2)

    // persistent registers: small columns + the edge-layer weights only
    float wnc[6], wd1c[6];
    {
        float4 t0 = *(const float4*)&wnT[lane * 12];
        float2 t1 = *(const float2*)&wnT[lane * 12 + 4];
        wnc[0]=t0.x; wnc[1]=t0.y; wnc[2]=t0.z; wnc[3]=t0.w; wnc[4]=t1.x; wnc[5]=t1.y;
        float4 s0 = *(const float4*)&wd1T[lane * 12];
        float2 s1 = *(const float2*)&wd1T[lane * 12 + 4];
        wd1c[0]=s0.x; wd1c[1]=s0.y; wd1c[2]=s0.z; wd1c[3]=s0.w; wd1c[4]=s1.x; wd1c[5]=s1.y;
    }
    float wu[32], wv[32];
#pragma unroll
    for (int t = 0; t < 8; t++) {
        LD4(we1T, wu + 4 * t, lane * 68 + 4 * t);
        LD4(we1T, wv + 4 * t, lane * 68 + 32 + 4 * t);
    }
    const float bnl = bnS[lane], be1l = be1S[lane];
    const float bd1l = bd1S[lane], bd2l = bd2S[lane], bs1l = bs1S[lane];
    const float bs2l = bs2S[lane & 15];
    const float ws3l = (lane < 16) ? ws3S[lane] : 0.0f;
    const float bd3l = bd3S[j1], bd3l2 = bd3S[j2];
    const float be2v = scal[0], bs3v = scal[1];

    const size_t predBase = (size_t)Btot * 36;
    const size_t scoreBase = (size_t)Btot * 72;

#pragma unroll 1
    for (int s = 0; s < SPW; s++) {
        const int b = (blockIdx.x * NW + w) * SPW + s;
        if (b < Btot) {
            // ---- stage factors into padded rows ----
            const float* fb = factors + (size_t)b * 36;
            float v1 = fb[lane];
            A[FSP + i1 * 8 + j1] = v1;
            if (lane < 4) A[FSP + 40 + j2] = fb[32 + lane];
            __syncwarp();

            // ---- node encoder: nf[i][lane] ----
#pragma unroll
            for (int i = 0; i < 6; i++) {
                float4 f4 = *(const float4*)&A[FSP + i * 8];
                float2 f2 = *(const float2*)&A[FSP + i * 8 + 4];
                float acc = bnl;
                acc = fmaf(f4.x, wnc[0], acc); acc = fmaf(f4.y, wnc[1], acc);
                acc = fmaf(f4.z, wnc[2], acc); acc = fmaf(f4.w, wnc[3], acc);
                acc = fmaf(f2.x, wnc[4], acc); acc = fmaf(f2.y, wnc[5], acc);
                A[ANF + i * 32 + lane] = acc;
            }
            __syncwarp();

            // ---- u,v (lane = hidden); be1 folded into u ----
#pragma unroll
            for (int i = 0; i < 6; i++) {
                float ui = be1l, vi = 0.0f;
#pragma unroll
                for (int t = 0; t < 8; t++) {
                    float4 nv = *(const float4*)&A[ANF + i * 32 + 4 * t];
                    FMA4(ui, nv, wu, 4 * t);
                    FMA4(vi, nv, wv, 4 * t);
                }
                A[AU + i * 36 + lane] = ui;
                A[AV + i * 36 + lane] = vi;
            }
            __syncwarp();

            // ---- adjacency (lane = edge): k-loop over hidden ----
            {
                float acc1 = 0.0f, acc2 = 0.0f;
#pragma unroll
                for (int t = 0; t < 8; t++) {
                    float4 w2 = *(const float4*)&we2S[4 * t];
                    float4 a1 = *(const float4*)&A[AU + i1 * 36 + 4 * t];
                    float4 b1 = *(const float4*)&A[AV + j1 * 36 + 4 * t];
                    acc1 = fmaf(fmaxf(a1.x + b1.x, 0.0f), w2.x, acc1);
                    acc1 = fmaf(fmaxf(a1.y + b1.y, 0.0f), w2.y, acc1);
                    acc1 = fmaf(fmaxf(a1.z + b1.z, 0.0f), w2.z, acc1);
                    acc1 = fmaf(fmaxf(a1.w + b1.w, 0.0f), w2.w, acc1);
                    float4 a2 = *(const float4*)&A[AU + 5 * 36 + 4 * t];
                    float4 b2 = *(const float4*)&A[AV + j2 * 36 + 4 * t];
                    acc2 = fmaf(fmaxf(a2.x + b2.x, 0.0f), w2.x, acc2);
                    acc2 = fmaf(fmaxf(a2.y + b2.y, 0.0f), w2.y, acc2);
                    acc2 = fmaf(fmaxf(a2.z + b2.z, 0.0f), w2.z, acc2);
                    acc2 = fmaf(fmaxf(a2.w + b2.w, 0.0f), w2.w, acc2);
                }
                float a1v = (i1 == j1) ? 0.0f : sigm(acc1 + be2v);
                float a2v = (lane == 3) ? 0.0f : sigm(acc2 + be2v);
                A[ADJ + i1 * 8 + j1] = a1v;
                out[(size_t)b * 36 + lane] = a1v;
                if (lane < 4) {
                    A[ADJ + 40 + j2] = a2v;
                    out[(size_t)b * 36 + 32 + lane] = a2v;
                }
            }
            __syncwarp();

            // ---- structured (lane = (n=i1, i=j1)): row dot6 ----
            {
                float4 ra4 = *(const float4*)&A[ADJ + j1 * 8];
                float2 ra2 = *(const float2*)&A[ADJ + j1 * 8 + 4];
                float4 rf4 = *(const float4*)&A[FSP + i1 * 8];
                float2 rf2 = *(const float2*)&A[FSP + i1 * 8 + 4];
                float sv = 0.0f;
                DOT6(sv, ra4, ra2, rf4, rf2);
                A[ASP + i1 * 8 + j1] = sv;
                if (lane < 4) {
                    float4 qa4 = *(const float4*)&A[ADJ + j2 * 8];
                    float2 qa2 = *(const float2*)&A[ADJ + j2 * 8 + 4];
                    float4 qf4 = *(const float4*)&A[FSP + 40];
                    float2 qf2 = *(const float2*)&A[FSP + 44];
                    float sv2 = 0.0f;
                    DOT6(sv2, qa4, qa2, qf4, qf2);
                    A[ASP + 40 + j2] = sv2;
                }
            }
            __syncwarp();

            // ---- h1 = relu(structured @ Wd1 + bd1) (lane = hidden) ----
#pragma unroll
            for (int n = 0; n < 6; n++) {
                float4 s4 = *(const float4*)&A[ASP + n * 8];
                float2 s2 = *(const float2*)&A[ASP + n * 8 + 4];
                float acc = bd1l;
                DOT6(acc, s4, s2, *(const float4*)&wd1c[0], *(const float2*)&wd1c[4]);
                A[ANF + n * 32 + lane] = fmaxf(acc, 0.0f);
            }
            __syncwarp();

            // ---- h2 = relu(h1 @ Wd2 + bd2) -> overlays u region ----
#pragma unroll
            for (int n = 0; n < 6; n++) {
                float acc = bd2l;
#pragma unroll
                for (int t = 0; t < 8; t++) {
                    float4 hv = *(const float4*)&A[ANF + n * 32 + 4 * t];
                    float4 wv2 = *(const float4*)&wd2T[lane * 36 + 4 * t];
                    FMA4V(acc, hv, wv2);
                }
                A[AU + n * 36 + lane] = fmaxf(acc, 0.0f);
            }
            __syncwarp();

            // ---- pred (lane = (n=i1, f=j1)): k-loop over hidden ----
            {
                float acc1 = 0.0f, acc2 = 0.0f;
#pragma unroll
                for (int t = 0; t < 8; t++) {
                    float4 hv = *(const float4*)&A[AU + i1 * 36 + 4 * t];
                    float4 w3a = *(const float4*)&wd3F[j1 * 36 + 4 * t];
                    FMA4V(acc1, hv, w3a);
                    float4 h5 = *(const float4*)&A[AU + 5 * 36 + 4 * t];
                    float4 w3b = *(const float4*)&wd3F[j2 * 36 + 4 * t];
                    FMA4V(acc2, h5, w3b);
                }
                float p1 = acc1 + bd3l;
                float p2 = acc2 + bd3l2;
                A[ASP + i1 * 8 + j1] = p1;   // pred overlays structured (dead)
                float* op = out + predBase + (size_t)b * 36;
                op[lane] = p1;
                if (lane < 4) {
                    A[ASP + 40 + j2] = p2;
                    op[32 + lane] = p2;
                }
            }
            __syncwarp();

            // ---- scorer layer 1 (lane = hidden) -> s1 in ANF ----
            {
                float ws1c[18];
#pragma unroll
                for (int t = 0; t < 4; t++) LD4(ws1T, ws1c + 4 * t, lane * 20 + 4 * t);
                {
                    float2 a = *(const float2*)&ws1T[lane * 20 + 16];
                    ws1c[16] = a.x; ws1c[17] = a.y;
                }
#pragma unroll
                for (int n = 0; n < 6; n++) {
                    float4 f4 = *(const float4*)&A[FSP + n * 8];
                    float2 f2 = *(const float2*)&A[FSP + n * 8 + 4];
                    float4 p4 = *(const float4*)&A[ASP + n * 8];
                    float2 p2 = *(const float2*)&A[ASP + n * 8 + 4];
                    float fk[6] = {f4.x, f4.y, f4.z, f4.w, f2.x, f2.y};
                    float pk[6] = {p4.x, p4.y, p4.z, p4.w, p2.x, p2.y};
                    float acc = bs1l;
#pragma unroll
                    for (int k = 0; k < 6; k++) {
                        acc = fmaf(fk[k], ws1c[k], acc);
                        acc = fmaf(pk[k], ws1c[6 + k], acc);
                        acc = fmaf(fabsf(fk[k] - pk[k]), ws1c[12 + k], acc);
                    }
                    A[ANF + n * 32 + lane] = fmaxf(acc, 0.0f);
                }
            }
            __syncwarp();

            // ---- scorer layers 2+3 ----
            float ssum = 0.0f;
#pragma unroll
            for (int n = 0; n < 6; n++) {
                float acc = bs2l;
#pragma unroll
                for (int t = 0; t < 8; t++) {
                    float4 sv = *(const float4*)&A[ANF + n * 32 + 4 * t];
                    float4 wv2 = *(const float4*)&ws2T[(lane & 15) * 36 + 4 * t];
                    FMA4V(acc, sv, wv2);
                }
                float tt = fmaxf(acc, 0.0f) * ws3l;  // lanes >= 16 contribute 0
                ssum += sigm(wsum(tt) + bs3v);
            }
            if (lane == 0) out[scoreBase + b] = ssum * (1.0f / 6.0f);
            __syncwarp();
        }
    }
}

extern "C" void kernel_launch(void* const* d_in, const int* in_sizes, int n_in,
                              void* d_out, int out_size) {
    const float* p[19];
    for (int i = 0; i < 19; i++) p[i] = (const float*)d_in[i];
    int Btot = in_sizes[0] / 36;
    int per_block = NW * SPW;
    int blocks = (Btot + per_block - 1) / per_block;
    cad_kernel<<<blocks, NW * 32>>>(
        p[0], p[1], p[2], p[3], p[4], p[5], p[6], p[7], p[8], p[9], p[10],
        p[11], p[12], p[13], p[14], p[15], p[16], p[17], p[18],
        (float*)d_out, Btot);
}

// round 6
// speedup vs baseline: 1.6492x; 1.0962x over previous
#include <cuda_runtime.h>

#define FULL 0xffffffffu
constexpr int NW = 8;    // warps per block
constexpr int SPW = 8;   // samples per warp

// per-warp activation region offsets (floats); all 16B-aligned
constexpr int FSP = 0;    // factors, 6 rows stride 8 (48)
constexpr int ANF = 48;   // nf / h1 / s1, i*32+lane (192)
constexpr int AU  = 240;  // u / h2, 6 rows stride 36
constexpr int AV  = 464;  // v, 6 rows stride 36
constexpr int ADJ = 680;  // adjacency, rows stride 8 (48)
constexpr int ASP = 728;  // structured / pred, rows stride 8 (48)
constexpr int ACT = 784;

__device__ __forceinline__ float sigm(float x) { return 1.0f / (1.0f + __expf(-x)); }

__device__ __forceinline__ float wsum(float t) {
#pragma unroll
    for (int o = 16; o; o >>= 1) t += __shfl_xor_sync(FULL, t, o);
    return t;
}

#define FMA4(acc, vec, arr, base)                  \
    acc = fmaf((vec).x, (arr)[(base) + 0], acc);   \
    acc = fmaf((vec).y, (arr)[(base) + 1], acc);   \
    acc = fmaf((vec).z, (arr)[(base) + 2], acc);   \
    acc = fmaf((vec).w, (arr)[(base) + 3], acc);

#define FMA4V(acc, vec, wv)                        \
    acc = fmaf((vec).x, (wv).x, acc);              \
    acc = fmaf((vec).y, (wv).y, acc);              \
    acc = fmaf((vec).z, (wv).z, acc);              \
    acc = fmaf((vec).w, (wv).w, acc);

#define LD4(arr, dst, off)                                        \
    { float4 _a = *(const float4*)&(arr)[off];                    \
      (dst)[0] = _a.x; (dst)[1] = _a.y; (dst)[2] = _a.z; (dst)[3] = _a.w; }

#define DOT6(acc, r4, r2, q4, q2)                  \
    acc = fmaf((r4).x, (q4).x, acc);               \
    acc = fmaf((r4).y, (q4).y, acc);               \
    acc = fmaf((r4).z, (q4).z, acc);               \
    acc = fmaf((r4).w, (q4).w, acc);               \
    acc = fmaf((r2).x, (q2).x, acc);               \
    acc = fmaf((r2).y, (q2).y, acc);

__global__ __launch_bounds__(NW * 32, 2) void cad_kernel(
    const float* __restrict__ factors,
    const float* __restrict__ Wn,  const float* __restrict__ bn,
    const float* __restrict__ We1, const float* __restrict__ be1,
    const float* __restrict__ We2, const float* __restrict__ be2,
    const float* __restrict__ Wd1, const float* __restrict__ bd1,
    const float* __restrict__ Wd2, const float* __restrict__ bd2,
    const float* __restrict__ Wd3, const float* __restrict__ bd3,
    const float* __restrict__ Ws1, const float* __restrict__ bs1,
    const float* __restrict__ Ws2, const float* __restrict__ bs2,
    const float* __restrict__ Ws3, const float* __restrict__ bs3,
    float* __restrict__ out, int Btot)
{
    __shared__ __align__(16) float wnT[32 * 12];
    __shared__ __align__(16) float we1T[32 * 68];
    __shared__ __align__(16) float wd1T[32 * 12];
    __shared__ __align__(16) float wd2T[32 * 36];
    __shared__ __align__(16) float wd3F[6 * 36];
    __shared__ __align__(16) float ws1T[32 * 20];
    __shared__ __align__(16) float ws2T[16 * 36];
    __shared__ __align__(16) float we2S[32];
    __shared__ float bnS[32], be1S[32], bd1S[32], bd2S[32], bs1S[32];
    __shared__ float bs2S[16], ws3S[16], bd3S[8], scal[2];
    __shared__ __align__(16) float act[NW][ACT];

    const int tid = threadIdx.x;

    for (int idx = tid; idx < 2048; idx += NW * 32) {
        int k = idx >> 5, l = idx & 31;
        we1T[l * 68 + k] = We1[idx];
    }
    for (int idx = tid; idx < 1024; idx += NW * 32) {
        int k = idx >> 5, l = idx & 31;
        wd2T[l * 36 + k] = Wd2[idx];
    }
    for (int idx = tid; idx < 576; idx += NW * 32) {
        int k = idx >> 5, l = idx & 31;
        ws1T[l * 20 + k] = Ws1[idx];
    }
    for (int idx = tid; idx < 512; idx += NW * 32) {
        int k = idx >> 4, m = idx & 15;
        ws2T[m * 36 + k] = Ws2[idx];
    }
    for (int idx = tid; idx < 192; idx += NW * 32) {
        int f = idx >> 5, l = idx & 31;
        wnT[l * 12 + f]  = Wn[idx];
        wd1T[l * 12 + f] = Wd1[idx];
        int k3 = idx / 6, f3 = idx - k3 * 6;
        wd3F[f3 * 36 + k3] = Wd3[idx];
    }
    if (tid < 32) {
        bnS[tid] = bn[tid];  be1S[tid] = be1[tid]; we2S[tid] = We2[tid];
        bd1S[tid] = bd1[tid]; bd2S[tid] = bd2[tid]; bs1S[tid] = bs1[tid];
    }
    if (tid < 16) { bs2S[tid] = bs2[tid]; ws3S[tid] = Ws3[tid]; }
    if (tid < 6)  { bd3S[tid] = bd3[tid]; }
    if (tid == 0) { scal[0] = be2[0]; scal[1] = bs3[0]; }
    __syncthreads();

    const int lane = tid & 31;
    const int w = tid >> 5;
    float* A = act[w];

    const int i1 = lane / 6, j1 = lane - i1 * 6;   // element e = lane
    const int j2 = (lane < 4) ? lane + 2 : 2;      // element 32+lane -> (5, j2)

    float wnc[6], wd1c[6];
    {
        float4 t0 = *(const float4*)&wnT[lane * 12];
        float2 t1 = *(const float2*)&wnT[lane * 12 + 4];
        wnc[0]=t0.x; wnc[1]=t0.y; wnc[2]=t0.z; wnc[3]=t0.w; wnc[4]=t1.x; wnc[5]=t1.y;
        float4 s0 = *(const float4*)&wd1T[lane * 12];
        float2 s1 = *(const float2*)&wd1T[lane * 12 + 4];
        wd1c[0]=s0.x; wd1c[1]=s0.y; wd1c[2]=s0.z; wd1c[3]=s0.w; wd1c[4]=s1.x; wd1c[5]=s1.y;
    }
    float wu[32], wv[32];
#pragma unroll
    for (int t = 0; t < 8; t++) {
        LD4(we1T, wu + 4 * t, lane * 68 + 4 * t);
        LD4(we1T, wv + 4 * t, lane * 68 + 32 + 4 * t);
    }
    const float bnl = bnS[lane], be1l = be1S[lane];
    const float bd1l = bd1S[lane], bd2l = bd2S[lane], bs1l = bs1S[lane];
    const float bs2l = bs2S[lane & 15];
    const float ws3l = (lane < 16) ? ws3S[lane] : 0.0f;
    const float bd3l = bd3S[j1], bd3l2 = bd3S[j2];
    const float be2v = scal[0], bs3v = scal[1];

    const size_t predBase = (size_t)Btot * 36;
    const size_t scoreBase = (size_t)Btot * 72;

#pragma unroll 1
    for (int s = 0; s < SPW; s++) {
        const int b = (blockIdx.x * NW + w) * SPW + s;
        if (b < Btot) {
            // ---- stage factors into padded rows ----
            const float* fb = factors + (size_t)b * 36;
            float v1 = fb[lane];
            A[FSP + i1 * 8 + j1] = v1;
            if (lane < 4) A[FSP + 40 + j2] = fb[32 + lane];
            __syncwarp();

            // ---- node encoder: nf[i][lane] ----
#pragma unroll
            for (int i = 0; i < 6; i++) {
                float4 f4 = *(const float4*)&A[FSP + i * 8];
                float2 f2 = *(const float2*)&A[FSP + i * 8 + 4];
                float acc = bnl;
                acc = fmaf(f4.x, wnc[0], acc); acc = fmaf(f4.y, wnc[1], acc);
                acc = fmaf(f4.z, wnc[2], acc); acc = fmaf(f4.w, wnc[3], acc);
                acc = fmaf(f2.x, wnc[4], acc); acc = fmaf(f2.y, wnc[5], acc);
                A[ANF + i * 32 + lane] = acc;
            }
            __syncwarp();

            // ---- u,v (lane = hidden); be1 folded into u ----
#pragma unroll
            for (int i = 0; i < 6; i++) {
                float ui = be1l, vi = 0.0f;
#pragma unroll
                for (int t = 0; t < 8; t++) {
                    float4 nv = *(const float4*)&A[ANF + i * 32 + 4 * t];
                    FMA4(ui, nv, wu, 4 * t);
                    FMA4(vi, nv, wv, 4 * t);
                }
                A[AU + i * 36 + lane] = ui;
                A[AV + i * 36 + lane] = vi;
            }
            __syncwarp();

            // ---- adjacency (lane = edge): k-loop over hidden ----
            {
                float acc1 = 0.0f, acc2 = 0.0f;
#pragma unroll
                for (int t = 0; t < 8; t++) {
                    float4 w2 = *(const float4*)&we2S[4 * t];
                    float4 a1 = *(const float4*)&A[AU + i1 * 36 + 4 * t];
                    float4 b1 = *(const float4*)&A[AV + j1 * 36 + 4 * t];
                    acc1 = fmaf(fmaxf(a1.x + b1.x, 0.0f), w2.x, acc1);
                    acc1 = fmaf(fmaxf(a1.y + b1.y, 0.0f), w2.y, acc1);
                    acc1 = fmaf(fmaxf(a1.z + b1.z, 0.0f), w2.z, acc1);
                    acc1 = fmaf(fmaxf(a1.w + b1.w, 0.0f), w2.w, acc1);
                    float4 a2 = *(const float4*)&A[AU + 5 * 36 + 4 * t];
                    float4 b2 = *(const float4*)&A[AV + j2 * 36 + 4 * t];
                    acc2 = fmaf(fmaxf(a2.x + b2.x, 0.0f), w2.x, acc2);
                    acc2 = fmaf(fmaxf(a2.y + b2.y, 0.0f), w2.y, acc2);
                    acc2 = fmaf(fmaxf(a2.z + b2.z, 0.0f), w2.z, acc2);
                    acc2 = fmaf(fmaxf(a2.w + b2.w, 0.0f), w2.w, acc2);
                }
                float a1v = (i1 == j1) ? 0.0f : sigm(acc1 + be2v);
                float a2v = (lane == 3) ? 0.0f : sigm(acc2 + be2v);
                A[ADJ + i1 * 8 + j1] = a1v;
                out[(size_t)b * 36 + lane] = a1v;
                if (lane < 4) {
                    A[ADJ + 40 + j2] = a2v;
                    out[(size_t)b * 36 + 32 + lane] = a2v;
                }
            }
            __syncwarp();

            // ---- structured (lane = (n=i1, i=j1)): row dot6 ----
            {
                float4 ra4 = *(const float4*)&A[ADJ + j1 * 8];
                float2 ra2 = *(const float2*)&A[ADJ + j1 * 8 + 4];
                float4 rf4 = *(const float4*)&A[FSP + i1 * 8];
                float2 rf2 = *(const float2*)&A[FSP + i1 * 8 + 4];
                float sv = 0.0f;
                DOT6(sv, ra4, ra2, rf4, rf2);
                A[ASP + i1 * 8 + j1] = sv;
                if (lane < 4) {
                    float4 qa4 = *(const float4*)&A[ADJ + j2 * 8];
                    float2 qa2 = *(const float2*)&A[ADJ + j2 * 8 + 4];
                    float4 qf4 = *(const float4*)&A[FSP + 40];
                    float2 qf2 = *(const float2*)&A[FSP + 44];
                    float sv2 = 0.0f;
                    DOT6(sv2, qa4, qa2, qf4, qf2);
                    A[ASP + 40 + j2] = sv2;
                }
            }
            __syncwarp();

            // ---- h1 = relu(structured @ Wd1 + bd1) (lane = hidden) ----
#pragma unroll
            for (int n = 0; n < 6; n++) {
                float4 s4 = *(const float4*)&A[ASP + n * 8];
                float2 s2 = *(const float2*)&A[ASP + n * 8 + 4];
                float acc = bd1l;
                DOT6(acc, s4, s2, *(const float4*)&wd1c[0], *(const float2*)&wd1c[4]);
                A[ANF + n * 32 + lane] = fmaxf(acc, 0.0f);
            }
            __syncwarp();

            // ---- h2 = relu(h1 @ Wd2 + bd2), INTERCHANGED: weight loaded once per t ----
            {
                float acc[6];
#pragma unroll
                for (int n = 0; n < 6; n++) acc[n] = bd2l;
#pragma unroll
                for (int t = 0; t < 8; t++) {
                    float4 wv2 = *(const float4*)&wd2T[lane * 36 + 4 * t];
#pragma unroll
                    for (int n = 0; n < 6; n++) {
                        float4 hv = *(const float4*)&A[ANF + n * 32 + 4 * t];
                        FMA4V(acc[n], hv, wv2);
                    }
                }
#pragma unroll
                for (int n = 0; n < 6; n++)
                    A[AU + n * 36 + lane] = fmaxf(acc[n], 0.0f);
            }
            __syncwarp();

            // ---- pred (lane = (n=i1, f=j1)): k-loop over hidden ----
            {
                float acc1 = 0.0f, acc2 = 0.0f;
#pragma unroll
                for (int t = 0; t < 8; t++) {
                    float4 hv = *(const float4*)&A[AU + i1 * 36 + 4 * t];
                    float4 w3a = *(const float4*)&wd3F[j1 * 36 + 4 * t];
                    FMA4V(acc1, hv, w3a);
                    float4 h5 = *(const float4*)&A[AU + 5 * 36 + 4 * t];
                    float4 w3b = *(const float4*)&wd3F[j2 * 36 + 4 * t];
                    FMA4V(acc2, h5, w3b);
                }
                float p1 = acc1 + bd3l;
                float p2 = acc2 + bd3l2;
                A[ASP + i1 * 8 + j1] = p1;
                float* op = out + predBase + (size_t)b * 36;
                op[lane] = p1;
                if (lane < 4) {
                    A[ASP + 40 + j2] = p2;
                    op[32 + lane] = p2;
                }
            }
            __syncwarp();

            // ---- scorer layer 1 (lane = hidden) -> s1 in ANF ----
            {
                float ws1c[18];
#pragma unroll
                for (int t = 0; t < 4; t++) LD4(ws1T, ws1c + 4 * t, lane * 20 + 4 * t);
                {
                    float2 a = *(const float2*)&ws1T[lane * 20 + 16];
                    ws1c[16] = a.x; ws1c[17] = a.y;
                }
#pragma unroll
                for (int n = 0; n < 6; n++) {
                    float4 f4 = *(const float4*)&A[FSP + n * 8];
                    float2 f2 = *(const float2*)&A[FSP + n * 8 + 4];
                    float4 p4 = *(const float4*)&A[ASP + n * 8];
                    float2 p2 = *(const float2*)&A[ASP + n * 8 + 4];
                    float fk[6] = {f4.x, f4.y, f4.z, f4.w, f2.x, f2.y};
                    float pk[6] = {p4.x, p4.y, p4.z, p4.w, p2.x, p2.y};
                    float acc = bs1l;
#pragma unroll
                    for (int k = 0; k < 6; k++) {
                        acc = fmaf(fk[k], ws1c[k], acc);
                        acc = fmaf(pk[k], ws1c[6 + k], acc);
                        acc = fmaf(fabsf(fk[k] - pk[k]), ws1c[12 + k], acc);
                    }
                    A[ANF + n * 32 + lane] = fmaxf(acc, 0.0f);
                }
            }
            __syncwarp();

            // ---- scorer layers 2+3, INTERCHANGED ----
            float ssum = 0.0f;
            {
                float acc[6];
#pragma unroll
                for (int n = 0; n < 6; n++) acc[n] = bs2l;
#pragma unroll
                for (int t = 0; t < 8; t++) {
                    float4 wv2 = *(const float4*)&ws2T[(lane & 15) * 36 + 4 * t];
#pragma unroll
                    for (int n = 0; n < 6; n++) {
                        float4 sv = *(const float4*)&A[ANF + n * 32 + 4 * t];
                        FMA4V(acc[n], sv, wv2);
                    }
                }
#pragma unroll
                for (int n = 0; n < 6; n++) {
                    float tt = fmaxf(acc[n], 0.0f) * ws3l;  // lanes >= 16 contribute 0
                    ssum += sigm(wsum(tt) + bs3v);
                }
            }
            if (lane == 0) out[scoreBase + b] = ssum * (1.0f / 6.0f);
            __syncwarp();
        }
    }
}

extern "C" void kernel_launch(void* const* d_in, const int* in_sizes, int n_in,
                              void* d_out, int out_size) {
    const float* p[19];
    for (int i = 0; i < 19; i++) p[i] = (const float*)d_in[i];
    int Btot = in_sizes[0] / 36;
    int per_block = NW * SPW;
    int blocks = (Btot + per_block - 1) / per_block;
    cad_kernel<<<blocks, NW * 32>>>(
        p[0], p[1], p[2], p[3], p[4], p[5], p[6], p[7], p[8], p[9], p[10],
        p[11], p[12], p[13], p[14], p[15], p[16], p[17], p[18],
        (float*)d_out, Btot);
}

// round 7
// speedup vs baseline: 1.7424x; 1.0565x over previous
#include <cuda_runtime.h>

#define FULL 0xffffffffu
constexpr int NW = 8;    // warps per block
constexpr int SPW = 8;   // samples per warp

// per-warp activation region offsets (floats); all 16B-aligned
constexpr int FSP = 0;    // factors, 6 rows stride 8 (48)
constexpr int ANF = 48;   // nf / h1 / s1, i*32+lane (192)
constexpr int AU  = 240;  // u / h2, 6 rows stride 36
constexpr int AV  = 464;  // v, 6 rows stride 36
constexpr int ADJ = 680;  // adjacency, rows stride 8 (48)
constexpr int ASP = 728;  // structured / pred, rows stride 8 (48)
constexpr int ACT = 784;

__device__ __forceinline__ float sigm(float x) { return 1.0f / (1.0f + __expf(-x)); }

__device__ __forceinline__ float wsum(float t) {
#pragma unroll
    for (int o = 16; o; o >>= 1) t += __shfl_xor_sync(FULL, t, o);
    return t;
}

#define FMA4V(acc, vec, wv)                        \
    acc = fmaf((vec).x, (wv).x, acc);              \
    acc = fmaf((vec).y, (wv).y, acc);              \
    acc = fmaf((vec).z, (wv).z, acc);              \
    acc = fmaf((vec).w, (wv).w, acc);

#define LD4(arr, dst, off)                                        \
    { float4 _a = *(const float4*)&(arr)[off];                    \
      (dst)[0] = _a.x; (dst)[1] = _a.y; (dst)[2] = _a.z; (dst)[3] = _a.w; }

#define DOT6(acc, r4, r2, q4, q2)                  \
    acc = fmaf((r4).x, (q4).x, acc);               \
    acc = fmaf((r4).y, (q4).y, acc);               \
    acc = fmaf((r4).z, (q4).z, acc);               \
    acc = fmaf((r4).w, (q4).w, acc);               \
    acc = fmaf((r2).x, (q2).x, acc);               \
    acc = fmaf((r2).y, (q2).y, acc);

__global__ __launch_bounds__(NW * 32, 3) void cad_kernel(
    const float* __restrict__ factors,
    const float* __restrict__ Wn,  const float* __restrict__ bn,
    const float* __restrict__ We1, const float* __restrict__ be1,
    const float* __restrict__ We2, const float* __restrict__ be2,
    const float* __restrict__ Wd1, const float* __restrict__ bd1,
    const float* __restrict__ Wd2, const float* __restrict__ bd2,
    const float* __restrict__ Wd3, const float* __restrict__ bd3,
    const float* __restrict__ Ws1, const float* __restrict__ bs1,
    const float* __restrict__ Ws2, const float* __restrict__ bs2,
    const float* __restrict__ Ws3, const float* __restrict__ bs3,
    float* __restrict__ out, int Btot)
{
    __shared__ __align__(16) float wnT[32 * 12];
    __shared__ __align__(16) float we1T[32 * 68];
    __shared__ __align__(16) float wd1T[32 * 12];
    __shared__ __align__(16) float wd2T[32 * 36];
    __shared__ __align__(16) float wd3F[6 * 36];
    __shared__ __align__(16) float ws1T[32 * 20];
    __shared__ __align__(16) float ws2T[16 * 36];
    __shared__ __align__(16) float we2S[32];
    __shared__ float bnS[32], be1S[32], bd1S[32], bd2S[32], bs1S[32];
    __shared__ float bs2S[16], ws3S[16], bd3S[8], scal[2];
    __shared__ __align__(16) float act[NW][ACT];

    const int tid = threadIdx.x;

    for (int idx = tid; idx < 2048; idx += NW * 32) {
        int k = idx >> 5, l = idx & 31;
        we1T[l * 68 + k] = We1[idx];
    }
    for (int idx = tid; idx < 1024; idx += NW * 32) {
        int k = idx >> 5, l = idx & 31;
        wd2T[l * 36 + k] = Wd2[idx];
    }
    for (int idx = tid; idx < 576; idx += NW * 32) {
        int k = idx >> 5, l = idx & 31;
        ws1T[l * 20 + k] = Ws1[idx];
    }
    for (int idx = tid; idx < 512; idx += NW * 32) {
        int k = idx >> 4, m = idx & 15;
        ws2T[m * 36 + k] = Ws2[idx];
    }
    for (int idx = tid; idx < 192; idx += NW * 32) {
        int f = idx >> 5, l = idx & 31;
        wnT[l * 12 + f]  = Wn[idx];
        wd1T[l * 12 + f] = Wd1[idx];
        int k3 = idx / 6, f3 = idx - k3 * 6;
        wd3F[f3 * 36 + k3] = Wd3[idx];
    }
    if (tid < 32) {
        bnS[tid] = bn[tid];  be1S[tid] = be1[tid]; we2S[tid] = We2[tid];
        bd1S[tid] = bd1[tid]; bd2S[tid] = bd2[tid]; bs1S[tid] = bs1[tid];
    }
    if (tid < 16) { bs2S[tid] = bs2[tid]; ws3S[tid] = Ws3[tid]; }
    if (tid < 6)  { bd3S[tid] = bd3[tid]; }
    if (tid == 0) { scal[0] = be2[0]; scal[1] = bs3[0]; }
    __syncthreads();

    const int lane = tid & 31;
    const int w = tid >> 5;
    float* A = act[w];

    const int i1 = lane / 6, j1 = lane - i1 * 6;   // element e = lane
    const int j2 = (lane < 4) ? lane + 2 : 2;      // element 32+lane -> (5, j2)

    float wnc[6], wd1c[6];
    {
        float4 t0 = *(const float4*)&wnT[lane * 12];
        float2 t1 = *(const float2*)&wnT[lane * 12 + 4];
        wnc[0]=t0.x; wnc[1]=t0.y; wnc[2]=t0.z; wnc[3]=t0.w; wnc[4]=t1.x; wnc[5]=t1.y;
        float4 s0 = *(const float4*)&wd1T[lane * 12];
        float2 s1 = *(const float2*)&wd1T[lane * 12 + 4];
        wd1c[0]=s0.x; wd1c[1]=s0.y; wd1c[2]=s0.z; wd1c[3]=s0.w; wd1c[4]=s1.x; wd1c[5]=s1.y;
    }
    const float bnl = bnS[lane], be1l = be1S[lane];
    const float bd1l = bd1S[lane], bd2l = bd2S[lane], bs1l = bs1S[lane];
    const float bs2l = bs2S[lane & 15];
    const float ws3l = (lane < 16) ? ws3S[lane] : 0.0f;
    const float bd3l = bd3S[j1], bd3l2 = bd3S[j2];
    const float be2v = scal[0], bs3v = scal[1];

    const size_t predBase = (size_t)Btot * 36;
    const size_t scoreBase = (size_t)Btot * 72;

#pragma unroll 1
    for (int s = 0; s < SPW; s++) {
        const int b = (blockIdx.x * NW + w) * SPW + s;
        if (b < Btot) {
            // ---- stage factors into padded rows ----
            const float* fb = factors + (size_t)b * 36;
            float v1 = fb[lane];
            A[FSP + i1 * 8 + j1] = v1;
            if (lane < 4) A[FSP + 40 + j2] = fb[32 + lane];
            __syncwarp();

            // ---- node encoder: nf[i][lane] ----
#pragma unroll
            for (int i = 0; i < 6; i++) {
                float4 f4 = *(const float4*)&A[FSP + i * 8];
                float2 f2 = *(const float2*)&A[FSP + i * 8 + 4];
                float acc = bnl;
                acc = fmaf(f4.x, wnc[0], acc); acc = fmaf(f4.y, wnc[1], acc);
                acc = fmaf(f4.z, wnc[2], acc); acc = fmaf(f4.w, wnc[3], acc);
                acc = fmaf(f2.x, wnc[4], acc); acc = fmaf(f2.y, wnc[5], acc);
                A[ANF + i * 32 + lane] = acc;
            }
            __syncwarp();

            // ---- u,v (lane = hidden), INTERCHANGED: weight quads loaded once per t ----
            {
                float uacc[6], vacc[6];
#pragma unroll
                for (int i = 0; i < 6; i++) { uacc[i] = be1l; vacc[i] = 0.0f; }
#pragma unroll
                for (int t = 0; t < 8; t++) {
                    float4 wuq = *(const float4*)&we1T[lane * 68 + 4 * t];
                    float4 wvq = *(const float4*)&we1T[lane * 68 + 32 + 4 * t];
#pragma unroll
                    for (int i = 0; i < 6; i++) {
                        float4 nv = *(const float4*)&A[ANF + i * 32 + 4 * t];
                        FMA4V(uacc[i], nv, wuq);
                        FMA4V(vacc[i], nv, wvq);
                    }
                }
#pragma unroll
                for (int i = 0; i < 6; i++) {
                    A[AU + i * 36 + lane] = uacc[i];
                    A[AV + i * 36 + lane] = vacc[i];
                }
            }
            __syncwarp();

            // ---- adjacency (lane = edge): k-loop over hidden ----
            {
                float acc1 = 0.0f, acc2 = 0.0f;
#pragma unroll
                for (int t = 0; t < 8; t++) {
                    float4 w2 = *(const float4*)&we2S[4 * t];
                    float4 a1 = *(const float4*)&A[AU + i1 * 36 + 4 * t];
                    float4 b1 = *(const float4*)&A[AV + j1 * 36 + 4 * t];
                    acc1 = fmaf(fmaxf(a1.x + b1.x, 0.0f), w2.x, acc1);
                    acc1 = fmaf(fmaxf(a1.y + b1.y, 0.0f), w2.y, acc1);
                    acc1 = fmaf(fmaxf(a1.z + b1.z, 0.0f), w2.z, acc1);
                    acc1 = fmaf(fmaxf(a1.w + b1.w, 0.0f), w2.w, acc1);
                    float4 a2 = *(const float4*)&A[AU + 5 * 36 + 4 * t];
                    float4 b2 = *(const float4*)&A[AV + j2 * 36 + 4 * t];
                    acc2 = fmaf(fmaxf(a2.x + b2.x, 0.0f), w2.x, acc2);
                    acc2 = fmaf(fmaxf(a2.y + b2.y, 0.0f), w2.y, acc2);
                    acc2 = fmaf(fmaxf(a2.z + b2.z, 0.0f), w2.z, acc2);
                    acc2 = fmaf(fmaxf(a2.w + b2.w, 0.0f), w2.w, acc2);
                }
                float a1v = (i1 == j1) ? 0.0f : sigm(acc1 + be2v);
                float a2v = (lane == 3) ? 0.0f : sigm(acc2 + be2v);
                A[ADJ + i1 * 8 + j1] = a1v;
                out[(size_t)b * 36 + lane] = a1v;
                if (lane < 4) {
                    A[ADJ + 40 + j2] = a2v;
                    out[(size_t)b * 36 + 32 + lane] = a2v;
                }
            }
            __syncwarp();

            // ---- structured (lane = (n=i1, i=j1)): row dot6 ----
            {
                float4 ra4 = *(const float4*)&A[ADJ + j1 * 8];
                float2 ra2 = *(const float2*)&A[ADJ + j1 * 8 + 4];
                float4 rf4 = *(const float4*)&A[FSP + i1 * 8];
                float2 rf2 = *(const float2*)&A[FSP + i1 * 8 + 4];
                float sv = 0.0f;
                DOT6(sv, ra4, ra2, rf4, rf2);
                A[ASP + i1 * 8 + j1] = sv;
                if (lane < 4) {
                    float4 qa4 = *(const float4*)&A[ADJ + j2 * 8];
                    float2 qa2 = *(const float2*)&A[ADJ + j2 * 8 + 4];
                    float4 qf4 = *(const float4*)&A[FSP + 40];
                    float2 qf2 = *(const float2*)&A[FSP + 44];
                    float sv2 = 0.0f;
                    DOT6(sv2, qa4, qa2, qf4, qf2);
                    A[ASP + 40 + j2] = sv2;
                }
            }
            __syncwarp();

            // ---- h1 = relu(structured @ Wd1 + bd1) (lane = hidden) ----
#pragma unroll
            for (int n = 0; n < 6; n++) {
                float4 s4 = *(const float4*)&A[ASP + n * 8];
                float2 s2 = *(const float2*)&A[ASP + n * 8 + 4];
                float acc = bd1l;
                DOT6(acc, s4, s2, *(const float4*)&wd1c[0], *(const float2*)&wd1c[4]);
                A[ANF + n * 32 + lane] = fmaxf(acc, 0.0f);
            }
            __syncwarp();

            // ---- h2 = relu(h1 @ Wd2 + bd2), INTERCHANGED ----
            {
                float acc[6];
#pragma unroll
                for (int n = 0; n < 6; n++) acc[n] = bd2l;
#pragma unroll
                for (int t = 0; t < 8; t++) {
                    float4 wv2 = *(const float4*)&wd2T[lane * 36 + 4 * t];
#pragma unroll
                    for (int n = 0; n < 6; n++) {
                        float4 hv = *(const float4*)&A[ANF + n * 32 + 4 * t];
                        FMA4V(acc[n], hv, wv2);
                    }
                }
#pragma unroll
                for (int n = 0; n < 6; n++)
                    A[AU + n * 36 + lane] = fmaxf(acc[n], 0.0f);
            }
            __syncwarp();

            // ---- pred (lane = (n=i1, f=j1)): k-loop over hidden ----
            {
                float acc1 = 0.0f, acc2 = 0.0f;
#pragma unroll
                for (int t = 0; t < 8; t++) {
                    float4 hv = *(const float4*)&A[AU + i1 * 36 + 4 * t];
                    float4 w3a = *(const float4*)&wd3F[j1 * 36 + 4 * t];
                    FMA4V(acc1, hv, w3a);
                    float4 h5 = *(const float4*)&A[AU + 5 * 36 + 4 * t];
                    float4 w3b = *(const float4*)&wd3F[j2 * 36 + 4 * t];
                    FMA4V(acc2, h5, w3b);
                }
                float p1 = acc1 + bd3l;
                float p2 = acc2 + bd3l2;
                A[ASP + i1 * 8 + j1] = p1;
                float* op = out + predBase + (size_t)b * 36;
                op[lane] = p1;
                if (lane < 4) {
                    A[ASP + 40 + j2] = p2;
                    op[32 + lane] = p2;
                }
            }
            __syncwarp();

            // ---- scorer layer 1 (lane = hidden) -> s1 in ANF ----
            {
                float ws1c[18];
#pragma unroll
                for (int t = 0; t < 4; t++) LD4(ws1T, ws1c + 4 * t, lane * 20 + 4 * t);
                {
                    float2 a = *(const float2*)&ws1T[lane * 20 + 16];
                    ws1c[16] = a.x; ws1c[17] = a.y;
                }
#pragma unroll
                for (int n = 0; n < 6; n++) {
                    float4 f4 = *(const float4*)&A[FSP + n * 8];
                    float2 f2 = *(const float2*)&A[FSP + n * 8 + 4];
                    float4 p4 = *(const float4*)&A[ASP + n * 8];
                    float2 p2 = *(const float2*)&A[ASP + n * 8 + 4];
                    float fk[6] = {f4.x, f4.y, f4.z, f4.w, f2.x, f2.y};
                    float pk[6] = {p4.x, p4.y, p4.z, p4.w, p2.x, p2.y};
                    float acc = bs1l;
#pragma unroll
                    for (int k = 0; k < 6; k++) {
                        acc = fmaf(fk[k], ws1c[k], acc);
                        acc = fmaf(pk[k], ws1c[6 + k], acc);
                        acc = fmaf(fabsf(fk[k] - pk[k]), ws1c[12 + k], acc);
                    }
                    A[ANF + n * 32 + lane] = fmaxf(acc, 0.0f);
                }
            }
            __syncwarp();

            // ---- scorer layers 2+3, INTERCHANGED ----
            float ssum = 0.0f;
            {
                float acc[6];
#pragma unroll
                for (int n = 0; n < 6; n++) acc[n] = bs2l;
#pragma unroll
                for (int t = 0; t < 8; t++) {
                    float4 wv2 = *(const float4*)&ws2T[(lane & 15) * 36 + 4 * t];
#pragma unroll
                    for (int n = 0; n < 6; n++) {
                        float4 sv = *(const float4*)&A[ANF + n * 32 + 4 * t];
                        FMA4V(acc[n], sv, wv2);
                    }
                }
#pragma unroll
                for (int n = 0; n < 6; n++) {
                    float tt = fmaxf(acc[n], 0.0f) * ws3l;  // lanes >= 16 contribute 0
                    ssum += sigm(wsum(tt) + bs3v);
                }
            }
            if (lane == 0) out[scoreBase + b] = ssum * (1.0f / 6.0f);
            __syncwarp();
        }
    }
}

extern "C" void kernel_launch(void* const* d_in, const int* in_sizes, int n_in,
                              void* d_out, int out_size) {
    const float* p[19];
    for (int i = 0; i < 19; i++) p[i] = (const float*)d_in[i];
    int Btot = in_sizes[0] / 36;
    int per_block = NW * SPW;
    int blocks = (Btot + per_block - 1) / per_block;
    cad_kernel<<<blocks, NW * 32>>>(
        p[0], p[1], p[2], p[3], p[4], p[5], p[6], p[7], p[8], p[9], p[10],
        p[11], p[12], p[13], p[14], p[15], p[16], p[17], p[18],
        (float*)d_out, Btot);
}